// round 1
// baseline (speedup 1.0000x reference)
#include <cuda_runtime.h>
#include <math.h>

#define BSZ 4096
#define IN_DIM 200
#define HID 512
#define OUTD 256
#define FREE 64
#define MEQ 128
#define MAX_ITER 20
#define F_TOL 1e-4f
#define LN_EPS 1e-5f

// ---------------- scratch (static device globals; no runtime allocation) ----
__device__ float g_bufA[BSZ * HID];
__device__ float g_bufB[BSZ * HID];
__device__ float g_ztmp[BSZ * OUTD];
__device__ float g_R[BSZ * MEQ];
__device__ float g_bias[OUTD];
__device__ float g_partial[512];
__device__ float g_bscale;
__device__ int   g_iter;
__device__ int   g_active;

// ---------------- control init: Bias = b_eq @ WbProj^T, bscale, iter/flag ---
__global__ void init_ctrl_kernel(const float* __restrict__ b_eq,
                                 const float* __restrict__ WbProj) {
    int t = threadIdx.x;  // 256
    if (t < OUTD) {
        float s = 0.f;
        #pragma unroll 4
        for (int m = 0; m < MEQ; m++) s = fmaf(b_eq[m], WbProj[t * MEQ + m], s);
        g_bias[t] = s;
    }
    if (t == 0) {
        float s = 0.f;
        for (int m = 0; m < MEQ; m++) { float v = b_eq[m]; s += v * v; }
        g_bscale = 1.0f + sqrtf(s);
        g_iter = 1;
        g_active = 1;
    }
}

// ---------------- tiled SGEMM: C = act(X[M,K] @ W[N,K]^T (+/-) bias) --------
// ACT: 0 = +bias, 1 = +bias,relu, 2 = +bias, relu for col>=FREE, 3 = -bias
// GATE: 0 none, 1 copy-X-tile-to-C when inactive (update step), 2 skip when inactive
template <int ACT, int GATE>
__global__ void gemm_kernel(const float* __restrict__ X,
                            const float* __restrict__ W,
                            const float* __restrict__ bias,
                            float* __restrict__ C,
                            int Ndim, int Kdim) {
    const int bm = blockIdx.y * 64;
    const int bn = blockIdx.x * 64;
    const int tid = threadIdx.x;  // 256

    if (GATE == 1 && !g_active) {
        // frozen iteration: preserve ping-pong by copying the tile through
        for (int i = tid; i < 64 * 64; i += 256) {
            int r = i >> 6, c = i & 63;
            C[(bm + r) * Ndim + bn + c] = X[(bm + r) * Kdim + bn + c];
        }
        return;
    }
    if (GATE == 2 && !g_active) return;

    __shared__ float As[16][68];
    __shared__ float Bs[16][68];

    const int tr = tid >> 4;  // 0..15 -> 4 rows each
    const int tc = tid & 15;  // 0..15 -> 4 cols each
    const int lr = tid >> 2;  // 0..63 load row
    const int cg = tid & 3;   // float4 group

    float acc[4][4] = {};

    for (int k0 = 0; k0 < Kdim; k0 += 16) {
        int kidx = k0 + cg * 4;
        // load X tile
        {
            const float* p = X + (bm + lr) * Kdim + kidx;
            float4 v;
            if (kidx + 3 < Kdim) v = *(const float4*)p;
            else {
                v.x = (kidx + 0 < Kdim) ? p[0] : 0.f;
                v.y = (kidx + 1 < Kdim) ? p[1] : 0.f;
                v.z = (kidx + 2 < Kdim) ? p[2] : 0.f;
                v.w = (kidx + 3 < Kdim) ? p[3] : 0.f;
            }
            As[cg * 4 + 0][lr] = v.x; As[cg * 4 + 1][lr] = v.y;
            As[cg * 4 + 2][lr] = v.z; As[cg * 4 + 3][lr] = v.w;
        }
        // load W tile
        {
            const float* p = W + (bn + lr) * Kdim + kidx;
            float4 v;
            if (kidx + 3 < Kdim) v = *(const float4*)p;
            else {
                v.x = (kidx + 0 < Kdim) ? p[0] : 0.f;
                v.y = (kidx + 1 < Kdim) ? p[1] : 0.f;
                v.z = (kidx + 2 < Kdim) ? p[2] : 0.f;
                v.w = (kidx + 3 < Kdim) ? p[3] : 0.f;
            }
            Bs[cg * 4 + 0][lr] = v.x; Bs[cg * 4 + 1][lr] = v.y;
            Bs[cg * 4 + 2][lr] = v.z; Bs[cg * 4 + 3][lr] = v.w;
        }
        __syncthreads();
        #pragma unroll
        for (int kk = 0; kk < 16; kk++) {
            float4 a = *(const float4*)&As[kk][tr * 4];
            float4 b = *(const float4*)&Bs[kk][tc * 4];
            acc[0][0] = fmaf(a.x, b.x, acc[0][0]); acc[0][1] = fmaf(a.x, b.y, acc[0][1]);
            acc[0][2] = fmaf(a.x, b.z, acc[0][2]); acc[0][3] = fmaf(a.x, b.w, acc[0][3]);
            acc[1][0] = fmaf(a.y, b.x, acc[1][0]); acc[1][1] = fmaf(a.y, b.y, acc[1][1]);
            acc[1][2] = fmaf(a.y, b.z, acc[1][2]); acc[1][3] = fmaf(a.y, b.w, acc[1][3]);
            acc[2][0] = fmaf(a.z, b.x, acc[2][0]); acc[2][1] = fmaf(a.z, b.y, acc[2][1]);
            acc[2][2] = fmaf(a.z, b.z, acc[2][2]); acc[2][3] = fmaf(a.z, b.w, acc[2][3]);
            acc[3][0] = fmaf(a.w, b.x, acc[3][0]); acc[3][1] = fmaf(a.w, b.y, acc[3][1]);
            acc[3][2] = fmaf(a.w, b.z, acc[3][2]); acc[3][3] = fmaf(a.w, b.w, acc[3][3]);
        }
        __syncthreads();
    }

    const int row = bm + tr * 4;
    const int col = bn + tc * 4;
    #pragma unroll
    for (int i = 0; i < 4; i++) {
        #pragma unroll
        for (int j = 0; j < 4; j++) {
            float v = acc[i][j];
            float b = bias[col + j];
            v = (ACT == 3) ? (v - b) : (v + b);
            if (ACT == 1) v = fmaxf(v, 0.f);
            if (ACT == 2 && (col + j) >= FREE) v = fmaxf(v, 0.f);
            C[(row + i) * Ndim + col + j] = v;
        }
    }
}

// ---------------- LayerNorm over last dim (512), in-place -------------------
__global__ void ln_kernel(float* __restrict__ H, const float* __restrict__ g,
                          const float* __restrict__ be) {
    const int row = blockIdx.x;
    float* h = H + row * HID;
    const int t = threadIdx.x;  // 256
    float v0 = h[t], v1 = h[t + 256];

    __shared__ float sw[8];
    __shared__ float s_mu, s_rstd;

    float s = v0 + v1;
    #pragma unroll
    for (int o = 16; o; o >>= 1) s += __shfl_down_sync(0xffffffffu, s, o);
    if ((t & 31) == 0) sw[t >> 5] = s;
    __syncthreads();
    if (t == 0) {
        float tot = 0.f;
        for (int i = 0; i < 8; i++) tot += sw[i];
        s_mu = tot * (1.0f / HID);
    }
    __syncthreads();
    const float mu = s_mu;
    float d0 = v0 - mu, d1 = v1 - mu;
    float q = d0 * d0 + d1 * d1;
    #pragma unroll
    for (int o = 16; o; o >>= 1) q += __shfl_down_sync(0xffffffffu, q, o);
    if ((t & 31) == 0) sw[t >> 5] = q;
    __syncthreads();
    if (t == 0) {
        float tot = 0.f;
        for (int i = 0; i < 8; i++) tot += sw[i];
        s_rstd = rsqrtf(tot * (1.0f / HID) + LN_EPS);
    }
    __syncthreads();
    const float rs = s_rstd;
    h[t]       = d0 * rs * g[t] + be[t];
    h[t + 256] = d1 * rs * g[t + 256] + be[t + 256];
}

// ---------------- per-row L2 norm of R[BSZ,MEQ], partial sums ---------------
__global__ void norm_kernel(const float* __restrict__ R) {
    if (!g_active) return;
    const int warp = threadIdx.x >> 5, lane = threadIdx.x & 31;
    const int row = blockIdx.x * 8 + warp;
    const float* r = R + row * MEQ;
    float q = 0.f;
    #pragma unroll
    for (int m = lane; m < MEQ; m += 32) { float v = r[m]; q = fmaf(v, v, q); }
    #pragma unroll
    for (int o = 16; o; o >>= 1) q += __shfl_down_sync(0xffffffffu, q, o);
    __shared__ float sn[8];
    if (lane == 0) sn[warp] = sqrtf(q);
    __syncthreads();
    if (threadIdx.x == 0) {
        float s = 0.f;
        for (int i = 0; i < 8; i++) s += sn[i];
        g_partial[blockIdx.x] = s;
    }
}

// ---------------- crit finalize + loop control ------------------------------
__global__ void finalize_kernel() {
    if (!g_active) return;
    const int t = threadIdx.x;  // 256
    float s = g_partial[t] + g_partial[t + 256];
    #pragma unroll
    for (int o = 16; o; o >>= 1) s += __shfl_down_sync(0xffffffffu, s, o);
    __shared__ float sw[8];
    if ((t & 31) == 0) sw[t >> 5] = s;
    __syncthreads();
    if (t == 0) {
        float tot = 0.f;
        for (int i = 0; i < 8; i++) tot += sw[i];
        float crit = tot * (1.0f / BSZ) / g_bscale;
        int it = g_iter + 1;
        g_iter = it;
        if (!((it <= MAX_ITER) && (crit > F_TOL))) g_active = 0;
    }
}

// ---------------- utility ----------------------------------------------------
__global__ void copy4_kernel(const float4* __restrict__ src, float4* __restrict__ dst, int n4) {
    int i = blockIdx.x * blockDim.x + threadIdx.x;
    if (i < n4) dst[i] = src[i];
}

__global__ void write_iter_kernel(float* __restrict__ out) {
    out[2 * BSZ * OUTD] = (float)g_iter;
}

// ---------------- launch -----------------------------------------------------
extern "C" void kernel_launch(void* const* d_in, const int* in_sizes, int n_in,
                              void* d_out, int out_size) {
    const float* x      = (const float*)d_in[0];
    const float* W0     = (const float*)d_in[1];
    const float* b0     = (const float*)d_in[2];
    const float* W1     = (const float*)d_in[3];
    const float* b1     = (const float*)d_in[4];
    const float* W2     = (const float*)d_in[5];
    const float* b2     = (const float*)d_in[6];
    const float* W3     = (const float*)d_in[7];
    const float* b3     = (const float*)d_in[8];
    const float* pW0    = (const float*)d_in[9];
    const float* pb0    = (const float*)d_in[10];
    const float* g0     = (const float*)d_in[11];
    const float* be0    = (const float*)d_in[12];
    const float* pW1    = (const float*)d_in[13];
    const float* pb1    = (const float*)d_in[14];
    const float* g1     = (const float*)d_in[15];
    const float* be1    = (const float*)d_in[16];
    const float* pWf    = (const float*)d_in[17];
    const float* pbf    = (const float*)d_in[18];
    const float* A      = (const float*)d_in[19];
    const float* b_eq   = (const float*)d_in[20];
    const float* WzProj = (const float*)d_in[21];
    const float* WbProj = (const float*)d_in[22];

    float* out = (float*)d_out;
    float* z_out = out;                 // z_star region, also loop buffer 0
    float* pz    = out + BSZ * OUTD;    // pz region

    float *bufA, *bufB, *ztmp, *Rbuf, *biasz;
    cudaGetSymbolAddress((void**)&bufA, g_bufA);
    cudaGetSymbolAddress((void**)&bufB, g_bufB);
    cudaGetSymbolAddress((void**)&ztmp, g_ztmp);
    cudaGetSymbolAddress((void**)&Rbuf, g_R);
    cudaGetSymbolAddress((void**)&biasz, g_bias);

    const dim3 tb(256);
    const dim3 gHID(HID / 64, BSZ / 64);   // N=512
    const dim3 gOUT(OUTD / 64, BSZ / 64);  // N=256
    const dim3 gMEQ(MEQ / 64, BSZ / 64);   // N=128

    init_ctrl_kernel<<<1, 256>>>(b_eq, WbProj);

    // optimality MLP
    gemm_kernel<1, 0><<<gHID, tb>>>(x,    W0, b0, bufA, HID, IN_DIM);
    gemm_kernel<1, 0><<<gHID, tb>>>(bufA, W1, b1, bufB, HID, HID);
    gemm_kernel<1, 0><<<gHID, tb>>>(bufB, W2, b2, bufA, HID, HID);
    gemm_kernel<0, 0><<<gOUT, tb>>>(bufA, W3, b3, bufB, OUTD, HID);  // z1 in bufB

    // projection net
    gemm_kernel<1, 0><<<gHID, tb>>>(bufB, pW0, pb0, bufA, HID, OUTD);
    ln_kernel<<<BSZ, 256>>>(bufA, g0, be0);
    gemm_kernel<1, 0><<<gHID, tb>>>(bufA, pW1, pb1, bufB, HID, HID);
    ln_kernel<<<BSZ, 256>>>(bufB, g1, be1);
    gemm_kernel<2, 0><<<gOUT, tb>>>(bufB, pWf, pbf, pz, OUTD, HID);  // pz (partial relu)

    // z <- pz
    copy4_kernel<<<(BSZ * OUTD / 4 + 255) / 256, 256>>>((const float4*)pz, (float4*)z_out,
                                                        BSZ * OUTD / 4);

    // fixed-point loop (20 static iterations, device-flag gated; ping-pong
    // z_out <-> ztmp so the final state always lands in z_out after iter 19)
    for (int k = 0; k < MAX_ITER; k++) {
        float* src = (k & 1) ? ztmp : z_out;
        float* dst = (k & 1) ? z_out : ztmp;
        gemm_kernel<2, 1><<<gOUT, tb>>>(src, WzProj, biasz, dst, OUTD, OUTD);
        gemm_kernel<3, 2><<<gMEQ, tb>>>(dst, A, b_eq, Rbuf, MEQ, OUTD);
        norm_kernel<<<BSZ / 8, 256>>>(Rbuf);
        finalize_kernel<<<1, 256>>>();
    }

    if (out_size > 2 * BSZ * OUTD) write_iter_kernel<<<1, 1>>>(out);
}

// round 3
// speedup vs baseline: 1.4449x; 1.4449x over previous
#include <cuda_runtime.h>
#include <cuda_bf16.h>
#include <cstdint>
#include <math.h>

#define BSZ 4096
#define IN_DIM 200
#define KPAD0 256
#define HID 512
#define OUTD 256
#define FREE 64
#define MEQ 128
#define MAX_ITER 20
#define F_TOL 1e-4f
#define LN_EPS 1e-5f

// smem tile geometry: 128 rows x 64 bf16, padded stride 72
#define TS 72
#define TILE_ELEMS (128 * TS)          // 9216 bf16
#define SMEM_BYTES (4 * TILE_ELEMS * 2) // 73728 B

// ======================= scratch =======================
struct Scratch {
    float bufA[BSZ * HID];
    float bufB[BSZ * HID];
    float ztmp[BSZ * OUTD];
    float bias[OUTD];
    float partial[32];
    __nv_bfloat16 xs_h[BSZ * KPAD0], xs_l[BSZ * KPAD0];
    __nv_bfloat16 aA_h[BSZ * HID],  aA_l[BSZ * HID];
    __nv_bfloat16 aB_h[BSZ * HID],  aB_l[BSZ * HID];
    __nv_bfloat16 z1_h[BSZ * OUTD], z1_l[BSZ * OUTD];
    __nv_bfloat16 lA_h[BSZ * HID],  lA_l[BSZ * HID];
    __nv_bfloat16 lB_h[BSZ * HID],  lB_l[BSZ * HID];
    __nv_bfloat16 zA_h[BSZ * OUTD], zA_l[BSZ * OUTD];
    __nv_bfloat16 zB_h[BSZ * OUTD], zB_l[BSZ * OUTD];
    __nv_bfloat16 w0h[HID * KPAD0], w0l[HID * KPAD0];
    __nv_bfloat16 w1h[HID * HID],   w1l[HID * HID];
    __nv_bfloat16 w2h[HID * HID],   w2l[HID * HID];
    __nv_bfloat16 w3h[OUTD * HID],  w3l[OUTD * HID];
    __nv_bfloat16 p0h[HID * OUTD],  p0l[HID * OUTD];
    __nv_bfloat16 p1h[HID * HID],   p1l[HID * HID];
    __nv_bfloat16 pfh[OUTD * HID],  pfl[OUTD * HID];
    __nv_bfloat16 Amh[MEQ * OUTD],  Aml[MEQ * OUTD];
    __nv_bfloat16 wzh[OUTD * OUTD], wzl[OUTD * OUTD];
};
__device__ Scratch S;
__device__ float g_bscale;
__device__ int g_iter;
__device__ int g_active;
__device__ int g_count;

// ======================= mma helper =======================
__device__ __forceinline__ void mma_bf16(float* d, const uint32_t* a, const uint32_t* b) {
    asm volatile(
        "mma.sync.aligned.m16n8k16.row.col.f32.bf16.bf16.f32 "
        "{%0,%1,%2,%3}, {%4,%5,%6,%7}, {%8,%9}, {%0,%1,%2,%3};\n"
        : "+f"(d[0]), "+f"(d[1]), "+f"(d[2]), "+f"(d[3])
        : "r"(a[0]), "r"(a[1]), "r"(a[2]), "r"(a[3]), "r"(b[0]), "r"(b[1]));
}

// ======================= small kernels =======================
__global__ void init_ctrl_kernel(const float* __restrict__ b_eq,
                                 const float* __restrict__ WbProj) {
    int t = threadIdx.x;
    if (t < OUTD) {
        float s = 0.f;
        #pragma unroll 4
        for (int m = 0; m < MEQ; m++) s = fmaf(b_eq[m], WbProj[t * MEQ + m], s);
        S.bias[t] = s;
    }
    if (t == 0) {
        float s = 0.f;
        for (int m = 0; m < MEQ; m++) { float v = b_eq[m]; s += v * v; }
        g_bscale = 1.0f + sqrtf(s);
        g_iter = 1;
        g_active = 1;
        g_count = 0;
    }
}

__global__ void split_pad_kernel(const float* __restrict__ src,
                                 __nv_bfloat16* __restrict__ h,
                                 __nv_bfloat16* __restrict__ l,
                                 int K, int Kp, int total) {
    int i = blockIdx.x * 256 + threadIdx.x;
    if (i >= total) return;
    int r = i / Kp, c = i - r * Kp;
    float v = (c < K) ? src[(size_t)r * K + c] : 0.f;
    __nv_bfloat16 hv = __float2bfloat16_rn(v);
    h[i] = hv;
    l[i] = __float2bfloat16_rn(v - __bfloat162float(hv));
}

__global__ void ln_split_kernel(const float* __restrict__ H,
                                const float* __restrict__ g, const float* __restrict__ be,
                                __nv_bfloat16* __restrict__ oh, __nv_bfloat16* __restrict__ ol) {
    const int row = blockIdx.x;
    const float* h = H + (size_t)row * HID;
    const int t = threadIdx.x;  // 256
    float v0 = h[t], v1 = h[t + 256];
    __shared__ float sw[8];
    __shared__ float s_mu, s_rstd;
    float s = v0 + v1;
    #pragma unroll
    for (int o = 16; o; o >>= 1) s += __shfl_down_sync(0xffffffffu, s, o);
    if ((t & 31) == 0) sw[t >> 5] = s;
    __syncthreads();
    if (t == 0) {
        float tot = 0.f;
        for (int i = 0; i < 8; i++) tot += sw[i];
        s_mu = tot * (1.0f / HID);
    }
    __syncthreads();
    const float mu = s_mu;
    float d0 = v0 - mu, d1 = v1 - mu;
    float q = d0 * d0 + d1 * d1;
    #pragma unroll
    for (int o = 16; o; o >>= 1) q += __shfl_down_sync(0xffffffffu, q, o);
    if ((t & 31) == 0) sw[t >> 5] = q;
    __syncthreads();
    if (t == 0) {
        float tot = 0.f;
        for (int i = 0; i < 8; i++) tot += sw[i];
        s_rstd = rsqrtf(tot * (1.0f / HID) + LN_EPS);
    }
    __syncthreads();
    const float rs = s_rstd;
    float y0 = d0 * rs * g[t] + be[t];
    float y1 = d1 * rs * g[t + 256] + be[t + 256];
    __nv_bfloat16 h0 = __float2bfloat16_rn(y0), h1 = __float2bfloat16_rn(y1);
    size_t base = (size_t)row * HID;
    oh[base + t] = h0;       ol[base + t] = __float2bfloat16_rn(y0 - __bfloat162float(h0));
    oh[base + t + 256] = h1; ol[base + t + 256] = __float2bfloat16_rn(y1 - __bfloat162float(h1));
}

__global__ void write_iter_kernel(float* __restrict__ out) {
    out[2 * BSZ * OUTD] = (float)g_iter;
}

// ======================= HMMA split-bf16 GEMM =======================
// C[4096 x Nt] = act( A[4096 x Kd] @ B[Nt x Kd]^T + bias )
// 3-product split: Ah*Bh + Ah*Bl + Al*Bh, fp32 accum.
// ACT: 0 none, 1 relu, 2 relu for col>=FREE
// GATE: 0 none, 1 copy srcF->outF when inactive, 2 skip when inactive
// NORM: residual mode: v = D - bias[col]; per-row L2 norms -> partial[by];
//       last block runs the finalize (crit, g_iter, g_active).
template <int ACT, int GATE, int WF32, int WSPLIT, int NORM>
__global__ void __launch_bounds__(256)
hgemm(const __nv_bfloat16* __restrict__ Ah_, const __nv_bfloat16* __restrict__ Al_,
      const __nv_bfloat16* __restrict__ Bh_, const __nv_bfloat16* __restrict__ Bl_,
      const float* __restrict__ bias, int Kd, int Nt,
      float* __restrict__ outF,
      __nv_bfloat16* __restrict__ oH, __nv_bfloat16* __restrict__ oL,
      const float* __restrict__ srcF) {
    const int tid = threadIdx.x;            // 256
    const int wid = tid >> 5, lane = tid & 31;
    const int l4 = lane >> 2, q4 = lane & 3;
    const int bm = blockIdx.y * 128, bn = blockIdx.x * 128;
    const int wm = (wid >> 2) * 64, wn = (wid & 3) * 32;

    if (GATE && !g_active) {
        if (GATE == 1) {
            for (int i = tid; i < 128 * 128; i += 256) {
                int r = i >> 7, c = i & 127;
                outF[(size_t)(bm + r) * Nt + bn + c] = srcF[(size_t)(bm + r) * Nt + bn + c];
            }
        }
        return;
    }

    extern __shared__ char smem[];
    __nv_bfloat16* sAH = (__nv_bfloat16*)smem;
    __nv_bfloat16* sAL = sAH + TILE_ELEMS;
    __nv_bfloat16* sBH = sAL + TILE_ELEMS;
    __nv_bfloat16* sBL = sBH + TILE_ELEMS;

    float acc[4][4][4] = {};
    const int nch = Kd >> 6;

    for (int ch = 0; ch < nch; ch++) {
        const int k0 = ch << 6;
        if (ch) __syncthreads();
        // stage 4 tiles (128x64 bf16 each)
        #pragma unroll
        for (int i = 0; i < 4; i++) {
            int idx = tid + i * 256;
            int r = idx >> 3, q = idx & 7;
            size_t goff = (size_t)r * Kd + k0 + q * 8;
            int soff = r * TS + q * 8;
            *(uint4*)(sAH + soff) = *(const uint4*)(Ah_ + (size_t)bm * Kd + goff);
            *(uint4*)(sAL + soff) = *(const uint4*)(Al_ + (size_t)bm * Kd + goff);
            *(uint4*)(sBH + soff) = *(const uint4*)(Bh_ + (size_t)bn * Kd + goff);
            *(uint4*)(sBL + soff) = *(const uint4*)(Bl_ + (size_t)bn * Kd + goff);
        }
        __syncthreads();

        #pragma unroll
        for (int ks = 0; ks < 4; ks++) {
            const int kc = ks * 16 + q4 * 2;   // bf16 col of this thread's frag
            uint32_t bh[4][2], bl[4][2];
            #pragma unroll
            for (int ni = 0; ni < 4; ni++) {
                int n = wn + ni * 8 + l4;
                bh[ni][0] = *(const uint32_t*)(sBH + n * TS + kc);
                bh[ni][1] = *(const uint32_t*)(sBH + n * TS + kc + 8);
                bl[ni][0] = *(const uint32_t*)(sBL + n * TS + kc);
                bl[ni][1] = *(const uint32_t*)(sBL + n * TS + kc + 8);
            }
            #pragma unroll
            for (int mi = 0; mi < 4; mi++) {
                int m = wm + mi * 16 + l4;
                uint32_t ah[4], al[4];
                ah[0] = *(const uint32_t*)(sAH + m * TS + kc);
                ah[1] = *(const uint32_t*)(sAH + (m + 8) * TS + kc);
                ah[2] = *(const uint32_t*)(sAH + m * TS + kc + 8);
                ah[3] = *(const uint32_t*)(sAH + (m + 8) * TS + kc + 8);
                al[0] = *(const uint32_t*)(sAL + m * TS + kc);
                al[1] = *(const uint32_t*)(sAL + (m + 8) * TS + kc);
                al[2] = *(const uint32_t*)(sAL + m * TS + kc + 8);
                al[3] = *(const uint32_t*)(sAL + (m + 8) * TS + kc + 8);
                #pragma unroll
                for (int ni = 0; ni < 4; ni++) {
                    mma_bf16(acc[mi][ni], ah, bh[ni]);
                    mma_bf16(acc[mi][ni], ah, bl[ni]);
                    mma_bf16(acc[mi][ni], al, bh[ni]);
                }
            }
        }
    }
    __syncthreads();

    if (NORM) {
        // residual: v = D - b_eq[col]; row L2 norms; fused finalize
        float* rowsq = (float*)smem;
        float* wsum = (float*)smem + 128;
        if (tid < 128) rowsq[tid] = 0.f;
        __syncthreads();
        #pragma unroll
        for (int mi = 0; mi < 4; mi++) {
            #pragma unroll
            for (int half = 0; half < 2; half++) {
                float s = 0.f;
                #pragma unroll
                for (int ni = 0; ni < 4; ni++) {
                    int c = wn + ni * 8 + q4 * 2;
                    float v0 = acc[mi][ni][half * 2 + 0] - bias[c];
                    float v1 = acc[mi][ni][half * 2 + 1] - bias[c + 1];
                    s = fmaf(v0, v0, fmaf(v1, v1, s));
                }
                s += __shfl_xor_sync(0xffffffffu, s, 1);
                s += __shfl_xor_sync(0xffffffffu, s, 2);
                if (q4 == 0) atomicAdd(&rowsq[wm + mi * 16 + half * 8 + l4], s);
            }
        }
        __syncthreads();
        float s = (tid < 128) ? sqrtf(rowsq[tid]) : 0.f;
        #pragma unroll
        for (int o = 16; o; o >>= 1) s += __shfl_down_sync(0xffffffffu, s, o);
        if (lane == 0) wsum[wid] = s;
        __syncthreads();
        if (tid == 0) {
            float tot = 0.f;
            #pragma unroll
            for (int i = 0; i < 8; i++) tot += wsum[i];
            S.partial[blockIdx.y] = tot;
            __threadfence();
            int c = atomicAdd(&g_count, 1);
            if (c == gridDim.y - 1) {
                __threadfence();
                float gs = 0.f;
                for (int i = 0; i < (int)gridDim.y; i++) gs += S.partial[i];
                float crit = gs * (1.0f / BSZ) / g_bscale;
                int it = g_iter + 1;
                g_iter = it;
                if (!((it <= MAX_ITER) && (crit > F_TOL))) g_active = 0;
                g_count = 0;
            }
        }
        return;
    }

    // normal epilogue
    #pragma unroll
    for (int mi = 0; mi < 4; mi++) {
        #pragma unroll
        for (int half = 0; half < 2; half++) {
            int r = bm + wm + mi * 16 + half * 8 + l4;
            #pragma unroll
            for (int ni = 0; ni < 4; ni++) {
                int c = bn + wn + ni * 8 + q4 * 2;
                float v0 = acc[mi][ni][half * 2 + 0] + bias[c];
                float v1 = acc[mi][ni][half * 2 + 1] + bias[c + 1];
                if (ACT == 1) { v0 = fmaxf(v0, 0.f); v1 = fmaxf(v1, 0.f); }
                if (ACT == 2) {
                    if (c >= FREE) v0 = fmaxf(v0, 0.f);
                    if (c + 1 >= FREE) v1 = fmaxf(v1, 0.f);
                }
                size_t base = (size_t)r * Nt + c;
                if (WF32) *(float2*)(outF + base) = make_float2(v0, v1);
                if (WSPLIT) {
                    __nv_bfloat16 h0 = __float2bfloat16_rn(v0);
                    __nv_bfloat16 h1 = __float2bfloat16_rn(v1);
                    uint32_t hp = (uint32_t)__bfloat16_as_ushort(h0) |
                                  ((uint32_t)__bfloat16_as_ushort(h1) << 16);
                    __nv_bfloat16 l0 = __float2bfloat16_rn(v0 - __bfloat162float(h0));
                    __nv_bfloat16 l1 = __float2bfloat16_rn(v1 - __bfloat162float(h1));
                    uint32_t lp = (uint32_t)__bfloat16_as_ushort(l0) |
                                  ((uint32_t)__bfloat16_as_ushort(l1) << 16);
                    *(uint32_t*)(oH + base) = hp;
                    *(uint32_t*)(oL + base) = lp;
                }
            }
        }
    }
}

// ======================= launch =======================
extern "C" void kernel_launch(void* const* d_in, const int* in_sizes, int n_in,
                              void* d_out, int out_size) {
    const float* x      = (const float*)d_in[0];
    const float* W0     = (const float*)d_in[1];
    const float* b0     = (const float*)d_in[2];
    const float* W1     = (const float*)d_in[3];
    const float* b1     = (const float*)d_in[4];
    const float* W2     = (const float*)d_in[5];
    const float* b2     = (const float*)d_in[6];
    const float* W3     = (const float*)d_in[7];
    const float* b3     = (const float*)d_in[8];
    const float* pW0    = (const float*)d_in[9];
    const float* pb0    = (const float*)d_in[10];
    const float* g0     = (const float*)d_in[11];
    const float* be0    = (const float*)d_in[12];
    const float* pW1    = (const float*)d_in[13];
    const float* pb1    = (const float*)d_in[14];
    const float* g1     = (const float*)d_in[15];
    const float* be1    = (const float*)d_in[16];
    const float* pWf    = (const float*)d_in[17];
    const float* pbf    = (const float*)d_in[18];
    const float* A      = (const float*)d_in[19];
    const float* b_eq   = (const float*)d_in[20];
    const float* WzProj = (const float*)d_in[21];
    const float* WbProj = (const float*)d_in[22];

    float* out = (float*)d_out;
    float* z_out = out;
    float* pz    = out + BSZ * OUTD;

    Scratch* sp;
    cudaGetSymbolAddress((void**)&sp, S);

    cudaFuncSetAttribute(hgemm<1, 0, 0, 1, 0>, cudaFuncAttributeMaxDynamicSharedMemorySize, SMEM_BYTES);
    cudaFuncSetAttribute(hgemm<0, 0, 0, 1, 0>, cudaFuncAttributeMaxDynamicSharedMemorySize, SMEM_BYTES);
    cudaFuncSetAttribute(hgemm<1, 0, 1, 0, 0>, cudaFuncAttributeMaxDynamicSharedMemorySize, SMEM_BYTES);
    cudaFuncSetAttribute(hgemm<2, 0, 1, 1, 0>, cudaFuncAttributeMaxDynamicSharedMemorySize, SMEM_BYTES);
    cudaFuncSetAttribute(hgemm<2, 1, 1, 1, 0>, cudaFuncAttributeMaxDynamicSharedMemorySize, SMEM_BYTES);
    cudaFuncSetAttribute(hgemm<0, 2, 0, 0, 1>, cudaFuncAttributeMaxDynamicSharedMemorySize, SMEM_BYTES);

    init_ctrl_kernel<<<1, 256>>>(b_eq, WbProj);

    const int TSPB = 256;
    #define SPLIT(src, h, l, R, K, Kp) \
        split_pad_kernel<<<((R) * (Kp) + TSPB - 1) / TSPB, TSPB>>>(src, h, l, K, Kp, (R) * (Kp))
    SPLIT(x,      sp->xs_h, sp->xs_l, BSZ, IN_DIM, KPAD0);
    SPLIT(W0,     sp->w0h,  sp->w0l,  HID, IN_DIM, KPAD0);
    SPLIT(W1,     sp->w1h,  sp->w1l,  HID, HID, HID);
    SPLIT(W2,     sp->w2h,  sp->w2l,  HID, HID, HID);
    SPLIT(W3,     sp->w3h,  sp->w3l,  OUTD, HID, HID);
    SPLIT(pW0,    sp->p0h,  sp->p0l,  HID, OUTD, OUTD);
    SPLIT(pW1,    sp->p1h,  sp->p1l,  HID, HID, HID);
    SPLIT(pWf,    sp->pfh,  sp->pfl,  OUTD, HID, HID);
    SPLIT(A,      sp->Amh,  sp->Aml,  MEQ, OUTD, OUTD);
    SPLIT(WzProj, sp->wzh,  sp->wzl,  OUTD, OUTD, OUTD);
    #undef SPLIT

    const dim3 tb(256);
    const dim3 gN512(4, 32), gN256(2, 32), gN128(1, 32);

    // feedforward MLP
    hgemm<1, 0, 0, 1, 0><<<gN512, tb, SMEM_BYTES>>>(sp->xs_h, sp->xs_l, sp->w0h, sp->w0l,
        b0, KPAD0, HID, nullptr, sp->aA_h, sp->aA_l, nullptr);
    hgemm<1, 0, 0, 1, 0><<<gN512, tb, SMEM_BYTES>>>(sp->aA_h, sp->aA_l, sp->w1h, sp->w1l,
        b1, HID, HID, nullptr, sp->aB_h, sp->aB_l, nullptr);
    hgemm<1, 0, 0, 1, 0><<<gN512, tb, SMEM_BYTES>>>(sp->aB_h, sp->aB_l, sp->w2h, sp->w2l,
        b2, HID, HID, nullptr, sp->aA_h, sp->aA_l, nullptr);
    hgemm<0, 0, 0, 1, 0><<<gN256, tb, SMEM_BYTES>>>(sp->aA_h, sp->aA_l, sp->w3h, sp->w3l,
        b3, HID, OUTD, nullptr, sp->z1_h, sp->z1_l, nullptr);

    // projection net
    hgemm<1, 0, 1, 0, 0><<<gN512, tb, SMEM_BYTES>>>(sp->z1_h, sp->z1_l, sp->p0h, sp->p0l,
        pb0, OUTD, HID, sp->bufA, nullptr, nullptr, nullptr);
    ln_split_kernel<<<BSZ, 256>>>(sp->bufA, g0, be0, sp->lA_h, sp->lA_l);
    hgemm<1, 0, 1, 0, 0><<<gN512, tb, SMEM_BYTES>>>(sp->lA_h, sp->lA_l, sp->p1h, sp->p1l,
        pb1, HID, HID, sp->bufB, nullptr, nullptr, nullptr);
    ln_split_kernel<<<BSZ, 256>>>(sp->bufB, g1, be1, sp->lB_h, sp->lB_l);
    hgemm<2, 0, 1, 1, 0><<<gN256, tb, SMEM_BYTES>>>(sp->lB_h, sp->lB_l, sp->pfh, sp->pfl,
        pbf, HID, OUTD, pz, sp->zA_h, sp->zA_l, nullptr);

    // fixed-point loop
    for (int k = 0; k < MAX_ITER; k++) {
        const __nv_bfloat16* inH = (k & 1) ? sp->zB_h : sp->zA_h;
        const __nv_bfloat16* inL = (k & 1) ? sp->zB_l : sp->zA_l;
        __nv_bfloat16* outH = (k & 1) ? sp->zA_h : sp->zB_h;
        __nv_bfloat16* outL = (k & 1) ? sp->zA_l : sp->zB_l;
        float* dstF = (k & 1) ? z_out : sp->ztmp;     // k=19 (odd) -> z_out
        const float* srcF = (k == 0) ? pz : ((k & 1) ? sp->ztmp : z_out);

        hgemm<2, 1, 1, 1, 0><<<gN256, tb, SMEM_BYTES>>>(inH, inL, sp->wzh, sp->wzl,
            sp->bias, OUTD, OUTD, dstF, outH, outL, srcF);
        hgemm<0, 2, 0, 0, 1><<<gN128, tb, SMEM_BYTES>>>(outH, outL, sp->Amh, sp->Aml,
            b_eq, OUTD, MEQ, nullptr, nullptr, nullptr, nullptr);
    }

    if (out_size > 2 * BSZ * OUTD) write_iter_kernel<<<1, 1>>>(out);
}

// round 4
// speedup vs baseline: 2.2509x; 1.5578x over previous
#include <cuda_runtime.h>
#include <cuda_bf16.h>
#include <cstdint>
#include <math.h>

#define BSZ 4096
#define IN_DIM 200
#define KPAD0 256
#define HID 512
#define OUTD 256
#define FREE 64
#define MEQ 128
#define MAX_ITER 20
#define F_TOL 1e-4f
#define LN_EPS 1e-5f

// feedforward hgemm tile geometry
#define TS 72
#define TILE_ELEMS (128 * TS)
#define SMEM_BYTES (4 * TILE_ELEMS * 2)

// persistent loop kernel geometry
#define PG 128               // grid (all co-resident: 1 CTA/SM)
#define PR 32                // z rows per CTA
#define ZST 264              // bf16 smem stride (132 words -> conflict-free frags)
#define SMEM_LOOP 135168

// ======================= scratch =======================
struct Scratch {
    float bufA[BSZ * HID];
    float bufB[BSZ * HID];
    float bias[OUTD];
    float partial[PG];
    __nv_bfloat16 xs_h[BSZ * KPAD0], xs_l[BSZ * KPAD0];
    __nv_bfloat16 aA_h[BSZ * HID],  aA_l[BSZ * HID];
    __nv_bfloat16 aB_h[BSZ * HID],  aB_l[BSZ * HID];
    __nv_bfloat16 z1_h[BSZ * OUTD], z1_l[BSZ * OUTD];
    __nv_bfloat16 lA_h[BSZ * HID],  lA_l[BSZ * HID];
    __nv_bfloat16 lB_h[BSZ * HID],  lB_l[BSZ * HID];
    __nv_bfloat16 w0h[HID * KPAD0], w0l[HID * KPAD0];
    __nv_bfloat16 w1h[HID * HID],   w1l[HID * HID];
    __nv_bfloat16 w2h[HID * HID],   w2l[HID * HID];
    __nv_bfloat16 w3h[OUTD * HID],  w3l[OUTD * HID];
    __nv_bfloat16 p0h[HID * OUTD],  p0l[HID * OUTD];
    __nv_bfloat16 p1h[HID * HID],   p1l[HID * HID];
    __nv_bfloat16 pfh[OUTD * HID],  pfl[OUTD * HID];
    __nv_bfloat16 Amh[MEQ * OUTD],  Aml[MEQ * OUTD];
    __nv_bfloat16 wzh[OUTD * OUTD], wzl[OUTD * OUTD];
};
__device__ Scratch S;
__device__ float g_bscale;
__device__ int g_iter;
__device__ int g_active;
__device__ int g_count;
__device__ int g_flag;

// ======================= mma helper =======================
__device__ __forceinline__ void mma_bf16(float* d, const uint32_t* a, const uint32_t* b) {
    asm volatile(
        "mma.sync.aligned.m16n8k16.row.col.f32.bf16.bf16.f32 "
        "{%0,%1,%2,%3}, {%4,%5,%6,%7}, {%8,%9}, {%0,%1,%2,%3};\n"
        : "+f"(d[0]), "+f"(d[1]), "+f"(d[2]), "+f"(d[3])
        : "r"(a[0]), "r"(a[1]), "r"(a[2]), "r"(a[3]), "r"(b[0]), "r"(b[1]));
}
__device__ __forceinline__ void split2(float v, __nv_bfloat16& h, __nv_bfloat16& l) {
    h = __float2bfloat16_rn(v);
    l = __float2bfloat16_rn(v - __bfloat162float(h));
}

// ======================= small kernels =======================
__global__ void init_ctrl_kernel(const float* __restrict__ b_eq,
                                 const float* __restrict__ WbProj) {
    int t = threadIdx.x;
    if (t < OUTD) {
        float s = 0.f;
        #pragma unroll 4
        for (int m = 0; m < MEQ; m++) s = fmaf(b_eq[m], WbProj[t * MEQ + m], s);
        S.bias[t] = s;
    }
    if (t == 0) {
        float s = 0.f;
        for (int m = 0; m < MEQ; m++) { float v = b_eq[m]; s += v * v; }
        g_bscale = 1.0f + sqrtf(s);
        g_iter = 1;
        g_active = 1;
        g_count = 0;
        g_flag = 0;
    }
}

__global__ void split_pad_kernel(const float* __restrict__ src,
                                 __nv_bfloat16* __restrict__ h,
                                 __nv_bfloat16* __restrict__ l,
                                 int K, int Kp, int total) {
    int i = blockIdx.x * 256 + threadIdx.x;
    if (i >= total) return;
    int r = i / Kp, c = i - r * Kp;
    float v = (c < K) ? src[(size_t)r * K + c] : 0.f;
    __nv_bfloat16 hv, lv;
    split2(v, hv, lv);
    h[i] = hv; l[i] = lv;
}

__global__ void ln_split_kernel(const float* __restrict__ H,
                                const float* __restrict__ g, const float* __restrict__ be,
                                __nv_bfloat16* __restrict__ oh, __nv_bfloat16* __restrict__ ol) {
    const int row = blockIdx.x;
    const float* h = H + (size_t)row * HID;
    const int t = threadIdx.x;  // 256
    float v0 = h[t], v1 = h[t + 256];
    __shared__ float sw[8];
    __shared__ float s_mu, s_rstd;
    float s = v0 + v1;
    #pragma unroll
    for (int o = 16; o; o >>= 1) s += __shfl_down_sync(0xffffffffu, s, o);
    if ((t & 31) == 0) sw[t >> 5] = s;
    __syncthreads();
    if (t == 0) {
        float tot = 0.f;
        for (int i = 0; i < 8; i++) tot += sw[i];
        s_mu = tot * (1.0f / HID);
    }
    __syncthreads();
    const float mu = s_mu;
    float d0 = v0 - mu, d1 = v1 - mu;
    float q = d0 * d0 + d1 * d1;
    #pragma unroll
    for (int o = 16; o; o >>= 1) q += __shfl_down_sync(0xffffffffu, q, o);
    if ((t & 31) == 0) sw[t >> 5] = q;
    __syncthreads();
    if (t == 0) {
        float tot = 0.f;
        for (int i = 0; i < 8; i++) tot += sw[i];
        s_rstd = rsqrtf(tot * (1.0f / HID) + LN_EPS);
    }
    __syncthreads();
    const float rs = s_rstd;
    float y0 = d0 * rs * g[t] + be[t];
    float y1 = d1 * rs * g[t + 256] + be[t + 256];
    __nv_bfloat16 h0, l0, h1, l1;
    split2(y0, h0, l0); split2(y1, h1, l1);
    size_t base = (size_t)row * HID;
    oh[base + t] = h0;       ol[base + t] = l0;
    oh[base + t + 256] = h1; ol[base + t + 256] = l1;
}

__global__ void write_iter_kernel(float* __restrict__ out) {
    out[2 * BSZ * OUTD] = (float)g_iter;
}

// ======================= HMMA split-bf16 GEMM (feedforward) =======================
template <int ACT, int WF32, int WSPLIT>
__global__ void __launch_bounds__(256)
hgemm(const __nv_bfloat16* __restrict__ Ah_, const __nv_bfloat16* __restrict__ Al_,
      const __nv_bfloat16* __restrict__ Bh_, const __nv_bfloat16* __restrict__ Bl_,
      const float* __restrict__ bias, int Kd, int Nt,
      float* __restrict__ outF,
      __nv_bfloat16* __restrict__ oH, __nv_bfloat16* __restrict__ oL) {
    const int tid = threadIdx.x;
    const int wid = tid >> 5, lane = tid & 31;
    const int l4 = lane >> 2, q4 = lane & 3;
    const int bm = blockIdx.y * 128, bn = blockIdx.x * 128;
    const int wm = (wid >> 2) * 64, wn = (wid & 3) * 32;

    extern __shared__ char smem[];
    __nv_bfloat16* sAH = (__nv_bfloat16*)smem;
    __nv_bfloat16* sAL = sAH + TILE_ELEMS;
    __nv_bfloat16* sBH = sAL + TILE_ELEMS;
    __nv_bfloat16* sBL = sBH + TILE_ELEMS;

    float acc[4][4][4] = {};
    const int nch = Kd >> 6;

    for (int ch = 0; ch < nch; ch++) {
        const int k0 = ch << 6;
        if (ch) __syncthreads();
        #pragma unroll
        for (int i = 0; i < 4; i++) {
            int idx = tid + i * 256;
            int r = idx >> 3, q = idx & 7;
            size_t goff = (size_t)r * Kd + k0 + q * 8;
            int soff = r * TS + q * 8;
            *(uint4*)(sAH + soff) = *(const uint4*)(Ah_ + (size_t)bm * Kd + goff);
            *(uint4*)(sAL + soff) = *(const uint4*)(Al_ + (size_t)bm * Kd + goff);
            *(uint4*)(sBH + soff) = *(const uint4*)(Bh_ + (size_t)bn * Kd + goff);
            *(uint4*)(sBL + soff) = *(const uint4*)(Bl_ + (size_t)bn * Kd + goff);
        }
        __syncthreads();

        #pragma unroll
        for (int ks = 0; ks < 4; ks++) {
            const int kc = ks * 16 + q4 * 2;
            uint32_t bh[4][2], bl[4][2];
            #pragma unroll
            for (int ni = 0; ni < 4; ni++) {
                int n = wn + ni * 8 + l4;
                bh[ni][0] = *(const uint32_t*)(sBH + n * TS + kc);
                bh[ni][1] = *(const uint32_t*)(sBH + n * TS + kc + 8);
                bl[ni][0] = *(const uint32_t*)(sBL + n * TS + kc);
                bl[ni][1] = *(const uint32_t*)(sBL + n * TS + kc + 8);
            }
            #pragma unroll
            for (int mi = 0; mi < 4; mi++) {
                int m = wm + mi * 16 + l4;
                uint32_t ah[4], al[4];
                ah[0] = *(const uint32_t*)(sAH + m * TS + kc);
                ah[1] = *(const uint32_t*)(sAH + (m + 8) * TS + kc);
                ah[2] = *(const uint32_t*)(sAH + m * TS + kc + 8);
                ah[3] = *(const uint32_t*)(sAH + (m + 8) * TS + kc + 8);
                al[0] = *(const uint32_t*)(sAL + m * TS + kc);
                al[1] = *(const uint32_t*)(sAL + (m + 8) * TS + kc);
                al[2] = *(const uint32_t*)(sAL + m * TS + kc + 8);
                al[3] = *(const uint32_t*)(sAL + (m + 8) * TS + kc + 8);
                #pragma unroll
                for (int ni = 0; ni < 4; ni++) {
                    mma_bf16(acc[mi][ni], ah, bh[ni]);
                    mma_bf16(acc[mi][ni], ah, bl[ni]);
                    mma_bf16(acc[mi][ni], al, bh[ni]);
                }
            }
        }
    }
    __syncthreads();

    #pragma unroll
    for (int mi = 0; mi < 4; mi++) {
        #pragma unroll
        for (int half = 0; half < 2; half++) {
            int r = bm + wm + mi * 16 + half * 8 + l4;
            #pragma unroll
            for (int ni = 0; ni < 4; ni++) {
                int c = bn + wn + ni * 8 + q4 * 2;
                float v0 = acc[mi][ni][half * 2 + 0] + bias[c];
                float v1 = acc[mi][ni][half * 2 + 1] + bias[c + 1];
                if (ACT == 1) { v0 = fmaxf(v0, 0.f); v1 = fmaxf(v1, 0.f); }
                if (ACT == 2) {
                    if (c >= FREE) v0 = fmaxf(v0, 0.f);
                    if (c + 1 >= FREE) v1 = fmaxf(v1, 0.f);
                }
                size_t base = (size_t)r * Nt + c;
                if (WF32) *(float2*)(outF + base) = make_float2(v0, v1);
                if (WSPLIT) {
                    __nv_bfloat16 h0, l0, h1, l1;
                    split2(v0, h0, l0); split2(v1, h1, l1);
                    *(uint32_t*)(oH + base) = (uint32_t)__bfloat16_as_ushort(h0) |
                                              ((uint32_t)__bfloat16_as_ushort(h1) << 16);
                    *(uint32_t*)(oL + base) = (uint32_t)__bfloat16_as_ushort(l0) |
                                              ((uint32_t)__bfloat16_as_ushort(l1) << 16);
                }
            }
        }
    }
}

// ======================= persistent fixed-point loop kernel =======================
// grid = 128 CTAs, each owns 32 rows of z, z resident in smem.
// per iteration: z = partial_relu(Bias + z @ Wz^T); r = z @ A^T - b_eq;
// per-row L2 norms -> deterministic grid reduction -> crit/iter/active.
__global__ void __launch_bounds__(256)
loop_kernel(const float* __restrict__ pz, float* __restrict__ z_out,
            const float* __restrict__ b_eq) {
    const int tid = threadIdx.x;
    const int wid = tid >> 5, lane = tid & 31;
    const int l4 = lane >> 2, q4 = lane & 3;
    const int wm = wid >> 2;      // 0..1 : rows [wm*16, +16)
    const int wn = wid & 3;       // 0..3 : cols [wn*16, +16) within 64-col block
    const int bid = blockIdx.x;
    const int rowbase = bid * PR;

    extern __shared__ char smem[];
    float* zf = (float*)smem;                                    // 32x256 f32
    __nv_bfloat16* zh = (__nv_bfloat16*)(smem + 32768);          // 32xZST
    __nv_bfloat16* zl = zh + PR * ZST;
    __nv_bfloat16* sh = zl + PR * ZST;                           // stage 64xZST
    __nv_bfloat16* sl = sh + 64 * ZST;
    float* red = (float*)(sl + 64 * ZST);                        // 128 floats
    __shared__ float s_fin[8];
    __shared__ int s_act;

    // init: load pz rows, split
    for (int i = tid; i < PR * 64; i += 256) {
        int r = i >> 6, c = (i & 63) * 4;
        float4 v = *(const float4*)(pz + (size_t)(rowbase + r) * OUTD + c);
        zf[r * 256 + c + 0] = v.x; zf[r * 256 + c + 1] = v.y;
        zf[r * 256 + c + 2] = v.z; zf[r * 256 + c + 3] = v.w;
        __nv_bfloat16 h, l;
        split2(v.x, h, l); zh[r * ZST + c + 0] = h; zl[r * ZST + c + 0] = l;
        split2(v.y, h, l); zh[r * ZST + c + 1] = h; zl[r * ZST + c + 1] = l;
        split2(v.z, h, l); zh[r * ZST + c + 2] = h; zl[r * ZST + c + 2] = l;
        split2(v.w, h, l); zh[r * ZST + c + 3] = h; zl[r * ZST + c + 3] = l;
    }
    __syncthreads();

    int ecn = 0;
    for (int e = 0; e < MAX_ITER; e++) {
        // ---------- phase U: z_new = Bias + z @ Wz^T (partial relu) ----------
        float accu[4][2][4];
        #pragma unroll
        for (int a = 0; a < 4; a++)
            #pragma unroll
            for (int b = 0; b < 2; b++)
                #pragma unroll
                for (int cc = 0; cc < 4; cc++) accu[a][b][cc] = 0.f;

        for (int nb = 0; nb < 4; nb++) {
            __syncthreads();
            // stage Wz rows [nb*64, +64) hi/lo
            for (int i = tid; i < 64 * 32; i += 256) {
                int r = i >> 5, c8 = (i & 31) * 8;
                *(uint4*)(sh + r * ZST + c8) = *(const uint4*)(S.wzh + (size_t)(nb * 64 + r) * OUTD + c8);
                *(uint4*)(sl + r * ZST + c8) = *(const uint4*)(S.wzl + (size_t)(nb * 64 + r) * OUTD + c8);
            }
            __syncthreads();
            #pragma unroll 4
            for (int ks = 0; ks < 16; ks++) {
                const int kc = ks * 16 + q4 * 2;
                const int m = wm * 16 + l4;
                uint32_t ah[4], al[4];
                ah[0] = *(const uint32_t*)(zh + m * ZST + kc);
                ah[1] = *(const uint32_t*)(zh + (m + 8) * ZST + kc);
                ah[2] = *(const uint32_t*)(zh + m * ZST + kc + 8);
                ah[3] = *(const uint32_t*)(zh + (m + 8) * ZST + kc + 8);
                al[0] = *(const uint32_t*)(zl + m * ZST + kc);
                al[1] = *(const uint32_t*)(zl + (m + 8) * ZST + kc);
                al[2] = *(const uint32_t*)(zl + m * ZST + kc + 8);
                al[3] = *(const uint32_t*)(zl + (m + 8) * ZST + kc + 8);
                #pragma unroll
                for (int ni = 0; ni < 2; ni++) {
                    int n = wn * 16 + ni * 8 + l4;
                    uint32_t bh[2], bl[2];
                    bh[0] = *(const uint32_t*)(sh + n * ZST + kc);
                    bh[1] = *(const uint32_t*)(sh + n * ZST + kc + 8);
                    bl[0] = *(const uint32_t*)(sl + n * ZST + kc);
                    bl[1] = *(const uint32_t*)(sl + n * ZST + kc + 8);
                    mma_bf16(accu[nb][ni], ah, bh);
                    mma_bf16(accu[nb][ni], ah, bl);
                    mma_bf16(accu[nb][ni], al, bh);
                }
            }
        }
        __syncthreads();   // all zh/zl reads done; safe to overwrite

        // epilogue U: bias + partial relu; write zf/zh/zl
        #pragma unroll
        for (int nb = 0; nb < 4; nb++) {
            #pragma unroll
            for (int ni = 0; ni < 2; ni++) {
                int c = nb * 64 + wn * 16 + ni * 8 + q4 * 2;
                int r0 = wm * 16 + l4, r1 = r0 + 8;
                float bv0 = S.bias[c], bv1 = S.bias[c + 1];
                float v00 = accu[nb][ni][0] + bv0;
                float v01 = accu[nb][ni][1] + bv1;
                float v10 = accu[nb][ni][2] + bv0;
                float v11 = accu[nb][ni][3] + bv1;
                if (c >= FREE)     { v00 = fmaxf(v00, 0.f); v10 = fmaxf(v10, 0.f); }
                if (c + 1 >= FREE) { v01 = fmaxf(v01, 0.f); v11 = fmaxf(v11, 0.f); }
                zf[r0 * 256 + c] = v00; zf[r0 * 256 + c + 1] = v01;
                zf[r1 * 256 + c] = v10; zf[r1 * 256 + c + 1] = v11;
                __nv_bfloat16 h, l;
                split2(v00, h, l); zh[r0 * ZST + c] = h;     zl[r0 * ZST + c] = l;
                split2(v01, h, l); zh[r0 * ZST + c + 1] = h; zl[r0 * ZST + c + 1] = l;
                split2(v10, h, l); zh[r1 * ZST + c] = h;     zl[r1 * ZST + c] = l;
                split2(v11, h, l); zh[r1 * ZST + c + 1] = h; zl[r1 * ZST + c + 1] = l;
            }
        }

        // ---------- phase R: residual norms ----------
        float sq0 = 0.f, sq1 = 0.f;
        for (int nb = 0; nb < 2; nb++) {
            __syncthreads();
            for (int i = tid; i < 64 * 32; i += 256) {
                int r = i >> 5, c8 = (i & 31) * 8;
                *(uint4*)(sh + r * ZST + c8) = *(const uint4*)(S.Amh + (size_t)(nb * 64 + r) * OUTD + c8);
                *(uint4*)(sl + r * ZST + c8) = *(const uint4*)(S.Aml + (size_t)(nb * 64 + r) * OUTD + c8);
            }
            __syncthreads();
            float accr[2][4] = {};
            #pragma unroll 4
            for (int ks = 0; ks < 16; ks++) {
                const int kc = ks * 16 + q4 * 2;
                const int m = wm * 16 + l4;
                uint32_t ah[4], al[4];
                ah[0] = *(const uint32_t*)(zh + m * ZST + kc);
                ah[1] = *(const uint32_t*)(zh + (m + 8) * ZST + kc);
                ah[2] = *(const uint32_t*)(zh + m * ZST + kc + 8);
                ah[3] = *(const uint32_t*)(zh + (m + 8) * ZST + kc + 8);
                al[0] = *(const uint32_t*)(zl + m * ZST + kc);
                al[1] = *(const uint32_t*)(zl + (m + 8) * ZST + kc);
                al[2] = *(const uint32_t*)(zl + m * ZST + kc + 8);
                al[3] = *(const uint32_t*)(zl + (m + 8) * ZST + kc + 8);
                #pragma unroll
                for (int ni = 0; ni < 2; ni++) {
                    int n = wn * 16 + ni * 8 + l4;
                    uint32_t bh[2], bl[2];
                    bh[0] = *(const uint32_t*)(sh + n * ZST + kc);
                    bh[1] = *(const uint32_t*)(sh + n * ZST + kc + 8);
                    bl[0] = *(const uint32_t*)(sl + n * ZST + kc);
                    bl[1] = *(const uint32_t*)(sl + n * ZST + kc + 8);
                    mma_bf16(accr[ni], ah, bh);
                    mma_bf16(accr[ni], ah, bl);
                    mma_bf16(accr[ni], al, bh);
                }
            }
            #pragma unroll
            for (int ni = 0; ni < 2; ni++) {
                int c = nb * 64 + wn * 16 + ni * 8 + q4 * 2;
                float b0 = b_eq[c], b1 = b_eq[c + 1];
                float v0 = accr[ni][0] - b0, v1 = accr[ni][1] - b1;
                float v2 = accr[ni][2] - b0, v3 = accr[ni][3] - b1;
                sq0 = fmaf(v0, v0, fmaf(v1, v1, sq0));
                sq1 = fmaf(v2, v2, fmaf(v3, v3, sq1));
            }
        }
        sq0 += __shfl_xor_sync(0xffffffffu, sq0, 1);
        sq0 += __shfl_xor_sync(0xffffffffu, sq0, 2);
        sq1 += __shfl_xor_sync(0xffffffffu, sq1, 1);
        sq1 += __shfl_xor_sync(0xffffffffu, sq1, 2);
        __syncthreads();
        if (q4 == 0) {
            red[wn * 32 + wm * 16 + l4] = sq0;
            red[wn * 32 + wm * 16 + 8 + l4] = sq1;
        }
        __syncthreads();
        if (tid < 32) {
            float ssq = red[tid] + red[32 + tid] + red[64 + tid] + red[96 + tid];
            float nrm = sqrtf(ssq);
            #pragma unroll
            for (int o = 16; o; o >>= 1) nrm += __shfl_down_sync(0xffffffffu, nrm, o);
            if (tid == 0) {
                S.partial[bid] = nrm;
                __threadfence();
                atomicAdd(&g_count, 1);
            }
        }

        // ---------- grid barrier + deterministic finalize ----------
        ecn++;
        if (bid == 0) {
            if (tid == 0) {
                while (*(volatile int*)&g_count < PG * ecn) {}
                __threadfence();
            }
            __syncthreads();
            float v = (tid < PG) ? S.partial[tid] : 0.f;
            #pragma unroll
            for (int o = 16; o; o >>= 1) v += __shfl_down_sync(0xffffffffu, v, o);
            if (lane == 0) s_fin[wid] = v;
            __syncthreads();
            if (tid == 0) {
                float tot = 0.f;
                #pragma unroll
                for (int i = 0; i < 8; i++) tot += s_fin[i];
                float crit = tot * (1.0f / BSZ) / g_bscale;
                int it = g_iter + 1;
                g_iter = it;
                g_active = ((it <= MAX_ITER) && (crit > F_TOL)) ? 1 : 0;
                __threadfence();
                *(volatile int*)&g_flag = ecn;
            }
        }
        if (tid == 0) {
            while (*(volatile int*)&g_flag < ecn) {}
            __threadfence();
            s_act = g_active;
        }
        __syncthreads();
        if (!s_act) break;
    }

    // write z_star
    __syncthreads();
    for (int i = tid; i < PR * 64; i += 256) {
        int r = i >> 6, c = (i & 63) * 4;
        float4 v;
        v.x = zf[r * 256 + c + 0]; v.y = zf[r * 256 + c + 1];
        v.z = zf[r * 256 + c + 2]; v.w = zf[r * 256 + c + 3];
        *(float4*)(z_out + (size_t)(rowbase + r) * OUTD + c) = v;
    }
}

// ======================= launch =======================
extern "C" void kernel_launch(void* const* d_in, const int* in_sizes, int n_in,
                              void* d_out, int out_size) {
    const float* x      = (const float*)d_in[0];
    const float* W0     = (const float*)d_in[1];
    const float* b0     = (const float*)d_in[2];
    const float* W1     = (const float*)d_in[3];
    const float* b1     = (const float*)d_in[4];
    const float* W2     = (const float*)d_in[5];
    const float* b2     = (const float*)d_in[6];
    const float* W3     = (const float*)d_in[7];
    const float* b3     = (const float*)d_in[8];
    const float* pW0    = (const float*)d_in[9];
    const float* pb0    = (const float*)d_in[10];
    const float* g0     = (const float*)d_in[11];
    const float* be0    = (const float*)d_in[12];
    const float* pW1    = (const float*)d_in[13];
    const float* pb1    = (const float*)d_in[14];
    const float* g1     = (const float*)d_in[15];
    const float* be1    = (const float*)d_in[16];
    const float* pWf    = (const float*)d_in[17];
    const float* pbf    = (const float*)d_in[18];
    const float* A      = (const float*)d_in[19];
    const float* b_eq   = (const float*)d_in[20];
    const float* WzProj = (const float*)d_in[21];
    const float* WbProj = (const float*)d_in[22];

    float* out = (float*)d_out;
    float* z_out = out;
    float* pz    = out + BSZ * OUTD;

    Scratch* sp;
    cudaGetSymbolAddress((void**)&sp, S);

    cudaFuncSetAttribute(hgemm<1, 0, 1>, cudaFuncAttributeMaxDynamicSharedMemorySize, SMEM_BYTES);
    cudaFuncSetAttribute(hgemm<0, 0, 1>, cudaFuncAttributeMaxDynamicSharedMemorySize, SMEM_BYTES);
    cudaFuncSetAttribute(hgemm<1, 1, 0>, cudaFuncAttributeMaxDynamicSharedMemorySize, SMEM_BYTES);
    cudaFuncSetAttribute(hgemm<2, 1, 0>, cudaFuncAttributeMaxDynamicSharedMemorySize, SMEM_BYTES);
    cudaFuncSetAttribute(loop_kernel, cudaFuncAttributeMaxDynamicSharedMemorySize, SMEM_LOOP);

    init_ctrl_kernel<<<1, 256>>>(b_eq, WbProj);

    const int TSPB = 256;
    #define SPLIT(src, h, l, R, K, Kp) \
        split_pad_kernel<<<((R) * (Kp) + TSPB - 1) / TSPB, TSPB>>>(src, h, l, K, Kp, (R) * (Kp))
    SPLIT(x,      sp->xs_h, sp->xs_l, BSZ, IN_DIM, KPAD0);
    SPLIT(W0,     sp->w0h,  sp->w0l,  HID, IN_DIM, KPAD0);
    SPLIT(W1,     sp->w1h,  sp->w1l,  HID, HID, HID);
    SPLIT(W2,     sp->w2h,  sp->w2l,  HID, HID, HID);
    SPLIT(W3,     sp->w3h,  sp->w3l,  OUTD, HID, HID);
    SPLIT(pW0,    sp->p0h,  sp->p0l,  HID, OUTD, OUTD);
    SPLIT(pW1,    sp->p1h,  sp->p1l,  HID, HID, HID);
    SPLIT(pWf,    sp->pfh,  sp->pfl,  OUTD, HID, HID);
    SPLIT(A,      sp->Amh,  sp->Aml,  MEQ, OUTD, OUTD);
    SPLIT(WzProj, sp->wzh,  sp->wzl,  OUTD, OUTD, OUTD);
    #undef SPLIT

    const dim3 tb(256);
    const dim3 gN512(4, 32), gN256(2, 32);

    // feedforward MLP
    hgemm<1, 0, 1><<<gN512, tb, SMEM_BYTES>>>(sp->xs_h, sp->xs_l, sp->w0h, sp->w0l,
        b0, KPAD0, HID, nullptr, sp->aA_h, sp->aA_l);
    hgemm<1, 0, 1><<<gN512, tb, SMEM_BYTES>>>(sp->aA_h, sp->aA_l, sp->w1h, sp->w1l,
        b1, HID, HID, nullptr, sp->aB_h, sp->aB_l);
    hgemm<1, 0, 1><<<gN512, tb, SMEM_BYTES>>>(sp->aB_h, sp->aB_l, sp->w2h, sp->w2l,
        b2, HID, HID, nullptr, sp->aA_h, sp->aA_l);
    hgemm<0, 0, 1><<<gN256, tb, SMEM_BYTES>>>(sp->aA_h, sp->aA_l, sp->w3h, sp->w3l,
        b3, HID, OUTD, nullptr, sp->z1_h, sp->z1_l);

    // projection net
    hgemm<1, 1, 0><<<gN512, tb, SMEM_BYTES>>>(sp->z1_h, sp->z1_l, sp->p0h, sp->p0l,
        pb0, OUTD, HID, sp->bufA, nullptr, nullptr);
    ln_split_kernel<<<BSZ, 256>>>(sp->bufA, g0, be0, sp->lA_h, sp->lA_l);
    hgemm<1, 1, 0><<<gN512, tb, SMEM_BYTES>>>(sp->lA_h, sp->lA_l, sp->p1h, sp->p1l,
        pb1, HID, HID, sp->bufB, nullptr, nullptr);
    ln_split_kernel<<<BSZ, 256>>>(sp->bufB, g1, be1, sp->lB_h, sp->lB_l);
    hgemm<2, 1, 0><<<gN256, tb, SMEM_BYTES>>>(sp->lB_h, sp->lB_l, sp->pfh, sp->pfl,
        pbf, HID, OUTD, pz, nullptr, nullptr);

    // fused persistent fixed-point loop (replaces 40 launches)
    loop_kernel<<<PG, 256, SMEM_LOOP>>>(pz, z_out, b_eq);

    if (out_size > 2 * BSZ * OUTD) write_iter_kernel<<<1, 1>>>(out);
}

// round 5
// speedup vs baseline: 2.6738x; 1.1879x over previous
#include <cuda_runtime.h>
#include <cuda_bf16.h>
#include <cstdint>
#include <math.h>

#define BSZ 4096
#define IN_DIM 200
#define KPAD0 256
#define HID 512
#define OUTD 256
#define FREE 64
#define MEQ 128
#define MAX_ITER 20
#define F_TOL 1e-4f
#define LN_EPS 1e-5f

// feedforward hgemm tile geometry (2-stage cp.async pipeline)
#define TS 72
#define TILE_ELEMS (128 * TS)
#define SMEM_FF (2 * 4 * TILE_ELEMS * 2)   // 147456 B

// persistent loop kernel geometry
#define PG 128
#define PR 32
#define ZST 264
#define SMEM_LOOP ((2 * PR * ZST + 4 * 64 * ZST) * 2 + 1024)  // ~170 KB

// ======================= scratch =======================
struct Scratch {
    float bufA[BSZ * HID];
    float bufB[BSZ * HID];
    float bias[OUTD];
    float partial[PG];
    __nv_bfloat16 xs_h[BSZ * KPAD0], xs_l[BSZ * KPAD0];
    __nv_bfloat16 aA_h[BSZ * HID],  aA_l[BSZ * HID];
    __nv_bfloat16 aB_h[BSZ * HID],  aB_l[BSZ * HID];
    __nv_bfloat16 z1_h[BSZ * OUTD], z1_l[BSZ * OUTD];
    __nv_bfloat16 lA_h[BSZ * HID],  lA_l[BSZ * HID];
    __nv_bfloat16 lB_h[BSZ * HID],  lB_l[BSZ * HID];
    __nv_bfloat16 w0h[HID * KPAD0], w0l[HID * KPAD0];
    __nv_bfloat16 w1h[HID * HID],   w1l[HID * HID];
    __nv_bfloat16 w2h[HID * HID],   w2l[HID * HID];
    __nv_bfloat16 w3h[OUTD * HID],  w3l[OUTD * HID];
    __nv_bfloat16 p0h[HID * OUTD],  p0l[HID * OUTD];
    __nv_bfloat16 p1h[HID * HID],   p1l[HID * HID];
    __nv_bfloat16 pfh[OUTD * HID],  pfl[OUTD * HID];
    __nv_bfloat16 Amh[MEQ * OUTD],  Aml[MEQ * OUTD];
    __nv_bfloat16 wzh[OUTD * OUTD], wzl[OUTD * OUTD];
};
__device__ Scratch S;
__device__ float g_bscale;
__device__ int g_iter;
__device__ int g_active;
__device__ int g_count;
__device__ int g_flag;

// ======================= helpers =======================
__device__ __forceinline__ uint32_t smem_u32(const void* p) {
    uint32_t a;
    asm("{ .reg .u64 t; cvta.to.shared.u64 t, %1; cvt.u32.u64 %0, t; }" : "=r"(a) : "l"(p));
    return a;
}
__device__ __forceinline__ void cp16(uint32_t saddr, const void* g) {
    asm volatile("cp.async.cg.shared.global [%0], [%1], 16;" :: "r"(saddr), "l"(g));
}
#define CP_COMMIT() asm volatile("cp.async.commit_group;" ::: "memory")
#define CP_WAIT1() asm volatile("cp.async.wait_group 1;" ::: "memory")
#define CP_WAIT0() asm volatile("cp.async.wait_group 0;" ::: "memory")

__device__ __forceinline__ void mma_bf16(float* d, const uint32_t* a, const uint32_t* b) {
    asm volatile(
        "mma.sync.aligned.m16n8k16.row.col.f32.bf16.bf16.f32 "
        "{%0,%1,%2,%3}, {%4,%5,%6,%7}, {%8,%9}, {%0,%1,%2,%3};\n"
        : "+f"(d[0]), "+f"(d[1]), "+f"(d[2]), "+f"(d[3])
        : "r"(a[0]), "r"(a[1]), "r"(a[2]), "r"(a[3]), "r"(b[0]), "r"(b[1]));
}
__device__ __forceinline__ void split2(float v, __nv_bfloat16& h, __nv_bfloat16& l) {
    h = __float2bfloat16_rn(v);
    l = __float2bfloat16_rn(v - __bfloat162float(h));
}

// ======================= small kernels =======================
__global__ void init_ctrl_kernel(const float* __restrict__ b_eq,
                                 const float* __restrict__ WbProj) {
    int t = threadIdx.x;
    if (t < OUTD) {
        float s = 0.f;
        #pragma unroll 4
        for (int m = 0; m < MEQ; m++) s = fmaf(b_eq[m], WbProj[t * MEQ + m], s);
        S.bias[t] = s;
    }
    if (t == 0) {
        float s = 0.f;
        for (int m = 0; m < MEQ; m++) { float v = b_eq[m]; s += v * v; }
        g_bscale = 1.0f + sqrtf(s);
        g_iter = 1;
        g_active = 1;
        g_count = 0;
        g_flag = 0;
    }
}

// one fused split for all tensors (segment if-chain over a global index)
#define SEG0 1048576   // x        4096x256 (K=200)
#define SEG1 1179648   // W0       512x256  (K=200)
#define SEG2 1441792   // W1       512x512
#define SEG3 1703936   // W2       512x512
#define SEG4 1835008   // W3       256x512
#define SEG5 1966080   // pW0      512x256
#define SEG6 2228224   // pW1      512x512
#define SEG7 2359296   // pWf      256x512
#define SEG8 2392064   // A        128x256
#define SEG9 2457600   // Wz       256x256
__global__ void split_all_kernel(const float* __restrict__ x,  const float* __restrict__ W0,
                                 const float* __restrict__ W1, const float* __restrict__ W2,
                                 const float* __restrict__ W3, const float* __restrict__ pW0,
                                 const float* __restrict__ pW1, const float* __restrict__ pWf,
                                 const float* __restrict__ A,  const float* __restrict__ Wz) {
    int i = blockIdx.x * 256 + threadIdx.x;
    if (i >= SEG9) return;
    const float* src; __nv_bfloat16 *h, *l; int K, Kp, local;
    if      (i < SEG0) { src = x;   h = S.xs_h; l = S.xs_l; K = IN_DIM; Kp = 256; local = i; }
    else if (i < SEG1) { src = W0;  h = S.w0h;  l = S.w0l;  K = IN_DIM; Kp = 256; local = i - SEG0; }
    else if (i < SEG2) { src = W1;  h = S.w1h;  l = S.w1l;  K = 512;    Kp = 512; local = i - SEG1; }
    else if (i < SEG3) { src = W2;  h = S.w2h;  l = S.w2l;  K = 512;    Kp = 512; local = i - SEG2; }
    else if (i < SEG4) { src = W3;  h = S.w3h;  l = S.w3l;  K = 512;    Kp = 512; local = i - SEG3; }
    else if (i < SEG5) { src = pW0; h = S.p0h;  l = S.p0l;  K = 256;    Kp = 256; local = i - SEG4; }
    else if (i < SEG6) { src = pW1; h = S.p1h;  l = S.p1l;  K = 512;    Kp = 512; local = i - SEG5; }
    else if (i < SEG7) { src = pWf; h = S.pfh;  l = S.pfl;  K = 512;    Kp = 512; local = i - SEG6; }
    else if (i < SEG8) { src = A;   h = S.Amh;  l = S.Aml;  K = 256;    Kp = 256; local = i - SEG7; }
    else               { src = Wz;  h = S.wzh;  l = S.wzl;  K = 256;    Kp = 256; local = i - SEG8; }
    int r = local / Kp, c = local - r * Kp;
    float v = (c < K) ? src[(size_t)r * K + c] : 0.f;
    __nv_bfloat16 hv, lv;
    split2(v, hv, lv);
    h[local] = hv; l[local] = lv;
}

__global__ void ln_split_kernel(const float* __restrict__ H,
                                const float* __restrict__ g, const float* __restrict__ be,
                                __nv_bfloat16* __restrict__ oh, __nv_bfloat16* __restrict__ ol) {
    const int row = blockIdx.x;
    const float* h = H + (size_t)row * HID;
    const int t = threadIdx.x;  // 256
    float v0 = h[t], v1 = h[t + 256];
    __shared__ float sw[8];
    __shared__ float s_mu, s_rstd;
    float s = v0 + v1;
    #pragma unroll
    for (int o = 16; o; o >>= 1) s += __shfl_down_sync(0xffffffffu, s, o);
    if ((t & 31) == 0) sw[t >> 5] = s;
    __syncthreads();
    if (t == 0) {
        float tot = 0.f;
        for (int i = 0; i < 8; i++) tot += sw[i];
        s_mu = tot * (1.0f / HID);
    }
    __syncthreads();
    const float mu = s_mu;
    float d0 = v0 - mu, d1 = v1 - mu;
    float q = d0 * d0 + d1 * d1;
    #pragma unroll
    for (int o = 16; o; o >>= 1) q += __shfl_down_sync(0xffffffffu, q, o);
    if ((t & 31) == 0) sw[t >> 5] = q;
    __syncthreads();
    if (t == 0) {
        float tot = 0.f;
        for (int i = 0; i < 8; i++) tot += sw[i];
        s_rstd = rsqrtf(tot * (1.0f / HID) + LN_EPS);
    }
    __syncthreads();
    const float rs = s_rstd;
    float y0 = d0 * rs * g[t] + be[t];
    float y1 = d1 * rs * g[t + 256] + be[t + 256];
    __nv_bfloat16 h0, l0, h1, l1;
    split2(y0, h0, l0); split2(y1, h1, l1);
    size_t base = (size_t)row * HID;
    oh[base + t] = h0;       ol[base + t] = l0;
    oh[base + t + 256] = h1; ol[base + t + 256] = l1;
}

__global__ void write_iter_kernel(float* __restrict__ out) {
    out[2 * BSZ * OUTD] = (float)g_iter;
}

// ======================= HMMA split-bf16 GEMM, 2-stage cp.async ==============
template <int ACT, int WF32, int WSPLIT>
__global__ void __launch_bounds__(256)
hgemm(const __nv_bfloat16* __restrict__ Ah_, const __nv_bfloat16* __restrict__ Al_,
      const __nv_bfloat16* __restrict__ Bh_, const __nv_bfloat16* __restrict__ Bl_,
      const float* __restrict__ bias, int Kd, int Nt,
      float* __restrict__ outF,
      __nv_bfloat16* __restrict__ oH, __nv_bfloat16* __restrict__ oL) {
    const int tid = threadIdx.x;
    const int wid = tid >> 5, lane = tid & 31;
    const int l4 = lane >> 2, q4 = lane & 3;
    const int bm = blockIdx.y * 128, bn = blockIdx.x * 128;
    const int wm = (wid >> 2) * 64, wn = (wid & 3) * 32;
    const int r0 = tid >> 3, q_ld = tid & 7;

    extern __shared__ char smem[];
    __nv_bfloat16* sb = (__nv_bfloat16*)smem;
    const uint32_t sbu = smem_u32(smem);

    float acc[4][4][4] = {};
    const int nch = Kd >> 6;

    #define FF_ISSUE(ch, st) do {                                                   \
        const int k0i = (ch) << 6;                                                  \
        _Pragma("unroll")                                                           \
        for (int i = 0; i < 4; i++) {                                               \
            const int r = r0 + 32 * i;                                              \
            const uint32_t so = sbu + (uint32_t)(((st) * 4 * TILE_ELEMS + r * TS + q_ld * 8) * 2); \
            const size_t ga = (size_t)(bm + r) * Kd + k0i + q_ld * 8;               \
            const size_t gb = (size_t)(bn + r) * Kd + k0i + q_ld * 8;               \
            cp16(so,                  Ah_ + ga);                                    \
            cp16(so + TILE_ELEMS * 2, Al_ + ga);                                    \
            cp16(so + TILE_ELEMS * 4, Bh_ + gb);                                    \
            cp16(so + TILE_ELEMS * 6, Bl_ + gb);                                    \
        }                                                                           \
    } while (0)

    FF_ISSUE(0, 0); CP_COMMIT();

    for (int ch = 0; ch < nch; ch++) {
        if (ch) __syncthreads();
        if (ch + 1 < nch) { FF_ISSUE(ch + 1, (ch + 1) & 1); CP_COMMIT(); CP_WAIT1(); }
        else CP_WAIT0();
        __syncthreads();

        const int st = ch & 1;
        const __nv_bfloat16* sAH = sb + st * 4 * TILE_ELEMS;
        const __nv_bfloat16* sAL = sAH + TILE_ELEMS;
        const __nv_bfloat16* sBH = sAL + TILE_ELEMS;
        const __nv_bfloat16* sBL = sBH + TILE_ELEMS;

        #pragma unroll
        for (int ks = 0; ks < 4; ks++) {
            const int kc = ks * 16 + q4 * 2;
            uint32_t bh[4][2], bl[4][2];
            #pragma unroll
            for (int ni = 0; ni < 4; ni++) {
                int n = wn + ni * 8 + l4;
                bh[ni][0] = *(const uint32_t*)(sBH + n * TS + kc);
                bh[ni][1] = *(const uint32_t*)(sBH + n * TS + kc + 8);
                bl[ni][0] = *(const uint32_t*)(sBL + n * TS + kc);
                bl[ni][1] = *(const uint32_t*)(sBL + n * TS + kc + 8);
            }
            #pragma unroll
            for (int mi = 0; mi < 4; mi++) {
                int m = wm + mi * 16 + l4;
                uint32_t ah[4], al[4];
                ah[0] = *(const uint32_t*)(sAH + m * TS + kc);
                ah[1] = *(const uint32_t*)(sAH + (m + 8) * TS + kc);
                ah[2] = *(const uint32_t*)(sAH + m * TS + kc + 8);
                ah[3] = *(const uint32_t*)(sAH + (m + 8) * TS + kc + 8);
                al[0] = *(const uint32_t*)(sAL + m * TS + kc);
                al[1] = *(const uint32_t*)(sAL + (m + 8) * TS + kc);
                al[2] = *(const uint32_t*)(sAL + m * TS + kc + 8);
                al[3] = *(const uint32_t*)(sAL + (m + 8) * TS + kc + 8);
                #pragma unroll
                for (int ni = 0; ni < 4; ni++) {
                    mma_bf16(acc[mi][ni], ah, bh[ni]);
                    mma_bf16(acc[mi][ni], ah, bl[ni]);
                    mma_bf16(acc[mi][ni], al, bh[ni]);
                }
            }
        }
    }
    #undef FF_ISSUE

    #pragma unroll
    for (int mi = 0; mi < 4; mi++) {
        #pragma unroll
        for (int half = 0; half < 2; half++) {
            int r = bm + wm + mi * 16 + half * 8 + l4;
            #pragma unroll
            for (int ni = 0; ni < 4; ni++) {
                int c = bn + wn + ni * 8 + q4 * 2;
                float v0 = acc[mi][ni][half * 2 + 0] + bias[c];
                float v1 = acc[mi][ni][half * 2 + 1] + bias[c + 1];
                if (ACT == 1) { v0 = fmaxf(v0, 0.f); v1 = fmaxf(v1, 0.f); }
                if (ACT == 2) {
                    if (c >= FREE) v0 = fmaxf(v0, 0.f);
                    if (c + 1 >= FREE) v1 = fmaxf(v1, 0.f);
                }
                size_t base = (size_t)r * Nt + c;
                if (WF32) *(float2*)(outF + base) = make_float2(v0, v1);
                if (WSPLIT) {
                    __nv_bfloat16 h0, l0, h1, l1;
                    split2(v0, h0, l0); split2(v1, h1, l1);
                    *(uint32_t*)(oH + base) = (uint32_t)__bfloat16_as_ushort(h0) |
                                              ((uint32_t)__bfloat16_as_ushort(h1) << 16);
                    *(uint32_t*)(oL + base) = (uint32_t)__bfloat16_as_ushort(l0) |
                                              ((uint32_t)__bfloat16_as_ushort(l1) << 16);
                }
            }
        }
    }
}

// ======================= persistent fixed-point loop ==========================
__global__ void __launch_bounds__(256)
loop_kernel(const float* __restrict__ pz, float* __restrict__ z_out,
            const float* __restrict__ b_eq) {
    const int tid = threadIdx.x;
    const int wid = tid >> 5, lane = tid & 31;
    const int l4 = lane >> 2, q4 = lane & 3;
    const int wm = wid >> 2;
    const int wn = wid & 3;
    const int bid = blockIdx.x;
    const int rowbase = bid * PR;

    extern __shared__ char smem[];
    __nv_bfloat16* zh = (__nv_bfloat16*)smem;          // 32 x ZST
    __nv_bfloat16* zl = zh + PR * ZST;
    __nv_bfloat16* stg = zl + PR * ZST;                // 2 stages x (sh, sl), 64 x ZST each
    float* red = (float*)(stg + 4 * 64 * ZST);         // 128 floats
    const uint32_t sbu = smem_u32(smem);
    const uint32_t stg_off = 2 * PR * ZST * 2;
    __shared__ float s_fin[8];
    __shared__ int s_act;

    #define WZ_ISSUE(nb, st) do {                                                       \
        _Pragma("unroll")                                                               \
        for (int i2 = 0; i2 < 8; i2++) {                                                \
            int ii = tid + i2 * 256;                                                    \
            int r = ii >> 5, c8 = (ii & 31) * 8;                                        \
            uint32_t so = sbu + stg_off + (uint32_t)((((st) * 2) * 64 * ZST + r * ZST + c8) * 2); \
            cp16(so,                S.wzh + (size_t)((nb) * 64 + r) * OUTD + c8);       \
            cp16(so + 64 * ZST * 2, S.wzl + (size_t)((nb) * 64 + r) * OUTD + c8);       \
        }                                                                               \
    } while (0)
    #define A_ISSUE(nb, st) do {                                                        \
        _Pragma("unroll")                                                               \
        for (int i2 = 0; i2 < 8; i2++) {                                                \
            int ii = tid + i2 * 256;                                                    \
            int r = ii >> 5, c8 = (ii & 31) * 8;                                        \
            uint32_t so = sbu + stg_off + (uint32_t)((((st) * 2) * 64 * ZST + r * ZST + c8) * 2); \
            cp16(so, S.Amh + (size_t)((nb) * 64 + r) * OUTD + c8);                      \
        }                                                                               \
    } while (0)

    // init: load pz rows, split into zh/zl
    for (int i = tid; i < PR * 64; i += 256) {
        int r = i >> 6, c = (i & 63) * 4;
        float4 v = *(const float4*)(pz + (size_t)(rowbase + r) * OUTD + c);
        __nv_bfloat16 h, l;
        split2(v.x, h, l); zh[r * ZST + c + 0] = h; zl[r * ZST + c + 0] = l;
        split2(v.y, h, l); zh[r * ZST + c + 1] = h; zl[r * ZST + c + 1] = l;
        split2(v.z, h, l); zh[r * ZST + c + 2] = h; zl[r * ZST + c + 2] = l;
        split2(v.w, h, l); zh[r * ZST + c + 3] = h; zl[r * ZST + c + 3] = l;
    }
    __syncthreads();

    int ecn = 0;
    for (int e = 0; e < MAX_ITER; e++) {
        // ---------- phase U: z_new = Bias + z @ Wz^T (partial relu) ----------
        float accu[4][2][4];
        #pragma unroll
        for (int a = 0; a < 4; a++)
            #pragma unroll
            for (int b = 0; b < 2; b++)
                #pragma unroll
                for (int cc = 0; cc < 4; cc++) accu[a][b][cc] = 0.f;

        WZ_ISSUE(0, 0); CP_COMMIT();
        for (int nb = 0; nb < 4; nb++) {
            if (nb) __syncthreads();
            if (nb + 1 < 4) { WZ_ISSUE(nb + 1, (nb + 1) & 1); CP_COMMIT(); CP_WAIT1(); }
            else CP_WAIT0();
            __syncthreads();
            const int st = nb & 1;
            const __nv_bfloat16* sh = stg + (st * 2) * 64 * ZST;
            const __nv_bfloat16* sl = sh + 64 * ZST;
            #pragma unroll 4
            for (int ks = 0; ks < 16; ks++) {
                const int kc = ks * 16 + q4 * 2;
                const int m = wm * 16 + l4;
                uint32_t ah[4], al[4];
                ah[0] = *(const uint32_t*)(zh + m * ZST + kc);
                ah[1] = *(const uint32_t*)(zh + (m + 8) * ZST + kc);
                ah[2] = *(const uint32_t*)(zh + m * ZST + kc + 8);
                ah[3] = *(const uint32_t*)(zh + (m + 8) * ZST + kc + 8);
                al[0] = *(const uint32_t*)(zl + m * ZST + kc);
                al[1] = *(const uint32_t*)(zl + (m + 8) * ZST + kc);
                al[2] = *(const uint32_t*)(zl + m * ZST + kc + 8);
                al[3] = *(const uint32_t*)(zl + (m + 8) * ZST + kc + 8);
                #pragma unroll
                for (int ni = 0; ni < 2; ni++) {
                    int n = wn * 16 + ni * 8 + l4;
                    uint32_t bh[2], bl[2];
                    bh[0] = *(const uint32_t*)(sh + n * ZST + kc);
                    bh[1] = *(const uint32_t*)(sh + n * ZST + kc + 8);
                    bl[0] = *(const uint32_t*)(sl + n * ZST + kc);
                    bl[1] = *(const uint32_t*)(sl + n * ZST + kc + 8);
                    mma_bf16(accu[nb][ni], ah, bh);
                    mma_bf16(accu[nb][ni], ah, bl);
                    mma_bf16(accu[nb][ni], al, bh);
                }
            }
        }
        __syncthreads();   // all zh/zl reads done; safe to overwrite

        // prefetch A chunk 0 while doing the epilogue
        A_ISSUE(0, 0); CP_COMMIT();

        // epilogue U: bias + partial relu; write zh/zl
        #pragma unroll
        for (int nb = 0; nb < 4; nb++) {
            #pragma unroll
            for (int ni = 0; ni < 2; ni++) {
                int c = nb * 64 + wn * 16 + ni * 8 + q4 * 2;
                int r0 = wm * 16 + l4, r1 = r0 + 8;
                float bv0 = S.bias[c], bv1 = S.bias[c + 1];
                float v00 = accu[nb][ni][0] + bv0;
                float v01 = accu[nb][ni][1] + bv1;
                float v10 = accu[nb][ni][2] + bv0;
                float v11 = accu[nb][ni][3] + bv1;
                if (c >= FREE)     { v00 = fmaxf(v00, 0.f); v10 = fmaxf(v10, 0.f); }
                if (c + 1 >= FREE) { v01 = fmaxf(v01, 0.f); v11 = fmaxf(v11, 0.f); }
                __nv_bfloat16 h, l;
                split2(v00, h, l); zh[r0 * ZST + c] = h;     zl[r0 * ZST + c] = l;
                split2(v01, h, l); zh[r0 * ZST + c + 1] = h; zl[r0 * ZST + c + 1] = l;
                split2(v10, h, l); zh[r1 * ZST + c] = h;     zl[r1 * ZST + c] = l;
                split2(v11, h, l); zh[r1 * ZST + c + 1] = h; zl[r1 * ZST + c + 1] = l;
            }
        }

        A_ISSUE(1, 1); CP_COMMIT();

        // ---------- phase R: residual norms (A hi only: 2 products) ----------
        float sq0 = 0.f, sq1 = 0.f;
        for (int nb = 0; nb < 2; nb++) {
            if (nb == 0) { CP_WAIT1(); } else { CP_WAIT0(); }
            __syncthreads();   // nb0: also makes epilogue zh/zl visible
            const int st = nb & 1;
            const __nv_bfloat16* sh = stg + (st * 2) * 64 * ZST;
            float accr[2][4] = {};
            #pragma unroll 4
            for (int ks = 0; ks < 16; ks++) {
                const int kc = ks * 16 + q4 * 2;
                const int m = wm * 16 + l4;
                uint32_t ah[4], al[4];
                ah[0] = *(const uint32_t*)(zh + m * ZST + kc);
                ah[1] = *(const uint32_t*)(zh + (m + 8) * ZST + kc);
                ah[2] = *(const uint32_t*)(zh + m * ZST + kc + 8);
                ah[3] = *(const uint32_t*)(zh + (m + 8) * ZST + kc + 8);
                al[0] = *(const uint32_t*)(zl + m * ZST + kc);
                al[1] = *(const uint32_t*)(zl + (m + 8) * ZST + kc);
                al[2] = *(const uint32_t*)(zl + m * ZST + kc + 8);
                al[3] = *(const uint32_t*)(zl + (m + 8) * ZST + kc + 8);
                #pragma unroll
                for (int ni = 0; ni < 2; ni++) {
                    int n = wn * 16 + ni * 8 + l4;
                    uint32_t bh[2];
                    bh[0] = *(const uint32_t*)(sh + n * ZST + kc);
                    bh[1] = *(const uint32_t*)(sh + n * ZST + kc + 8);
                    mma_bf16(accr[ni], ah, bh);
                    mma_bf16(accr[ni], al, bh);
                }
            }
            #pragma unroll
            for (int ni = 0; ni < 2; ni++) {
                int c = nb * 64 + wn * 16 + ni * 8 + q4 * 2;
                float b0 = b_eq[c], b1 = b_eq[c + 1];
                float v0 = accr[ni][0] - b0, v1 = accr[ni][1] - b1;
                float v2 = accr[ni][2] - b0, v3 = accr[ni][3] - b1;
                sq0 = fmaf(v0, v0, fmaf(v1, v1, sq0));
                sq1 = fmaf(v2, v2, fmaf(v3, v3, sq1));
            }
        }
        sq0 += __shfl_xor_sync(0xffffffffu, sq0, 1);
        sq0 += __shfl_xor_sync(0xffffffffu, sq0, 2);
        sq1 += __shfl_xor_sync(0xffffffffu, sq1, 1);
        sq1 += __shfl_xor_sync(0xffffffffu, sq1, 2);
        __syncthreads();
        if (q4 == 0) {
            red[wn * 32 + wm * 16 + l4] = sq0;
            red[wn * 32 + wm * 16 + 8 + l4] = sq1;
        }
        __syncthreads();
        if (tid < 32) {
            float ssq = red[tid] + red[32 + tid] + red[64 + tid] + red[96 + tid];
            float nrm = sqrtf(ssq);
            #pragma unroll
            for (int o = 16; o; o >>= 1) nrm += __shfl_down_sync(0xffffffffu, nrm, o);
            if (tid == 0) {
                S.partial[bid] = nrm;
                __threadfence();
                atomicAdd(&g_count, 1);
            }
        }

        // ---------- grid barrier + deterministic finalize ----------
        ecn++;
        if (bid == 0) {
            if (tid == 0) {
                while (*(volatile int*)&g_count < PG * ecn) {}
                __threadfence();
            }
            __syncthreads();
            float v = (tid < PG) ? S.partial[tid] : 0.f;
            #pragma unroll
            for (int o = 16; o; o >>= 1) v += __shfl_down_sync(0xffffffffu, v, o);
            if (lane == 0) s_fin[wid] = v;
            __syncthreads();
            if (tid == 0) {
                float tot = 0.f;
                #pragma unroll
                for (int i = 0; i < 8; i++) tot += s_fin[i];
                float crit = tot * (1.0f / BSZ) / g_bscale;
                int it = g_iter + 1;
                g_iter = it;
                g_active = ((it <= MAX_ITER) && (crit > F_TOL)) ? 1 : 0;
                __threadfence();
                *(volatile int*)&g_flag = ecn;
            }
        }
        if (tid == 0) {
            while (*(volatile int*)&g_flag < ecn) {}
            __threadfence();
            s_act = g_active;
        }
        __syncthreads();
        if (!s_act) break;
    }

    // write z_star (reconstruct f32 = hi + lo)
    __syncthreads();
    for (int i = tid; i < PR * 256; i += 256) {
        int r = i >> 8, c = i & 255;
        z_out[(size_t)(rowbase + r) * OUTD + c] =
            __bfloat162float(zh[r * ZST + c]) + __bfloat162float(zl[r * ZST + c]);
    }
    #undef WZ_ISSUE
    #undef A_ISSUE
}

// ======================= launch =======================
extern "C" void kernel_launch(void* const* d_in, const int* in_sizes, int n_in,
                              void* d_out, int out_size) {
    const float* x      = (const float*)d_in[0];
    const float* W0     = (const float*)d_in[1];
    const float* b0     = (const float*)d_in[2];
    const float* W1     = (const float*)d_in[3];
    const float* b1     = (const float*)d_in[4];
    const float* W2     = (const float*)d_in[5];
    const float* b2     = (const float*)d_in[6];
    const float* W3     = (const float*)d_in[7];
    const float* b3     = (const float*)d_in[8];
    const float* pW0    = (const float*)d_in[9];
    const float* pb0    = (const float*)d_in[10];
    const float* g0     = (const float*)d_in[11];
    const float* be0    = (const float*)d_in[12];
    const float* pW1    = (const float*)d_in[13];
    const float* pb1    = (const float*)d_in[14];
    const float* g1     = (const float*)d_in[15];
    const float* be1    = (const float*)d_in[16];
    const float* pWf    = (const float*)d_in[17];
    const float* pbf    = (const float*)d_in[18];
    const float* A      = (const float*)d_in[19];
    const float* b_eq   = (const float*)d_in[20];
    const float* WzProj = (const float*)d_in[21];
    const float* WbProj = (const float*)d_in[22];

    float* out = (float*)d_out;
    float* z_out = out;
    float* pz    = out + BSZ * OUTD;

    Scratch* sp;
    cudaGetSymbolAddress((void**)&sp, S);

    cudaFuncSetAttribute(hgemm<1, 0, 1>, cudaFuncAttributeMaxDynamicSharedMemorySize, SMEM_FF);
    cudaFuncSetAttribute(hgemm<0, 0, 1>, cudaFuncAttributeMaxDynamicSharedMemorySize, SMEM_FF);
    cudaFuncSetAttribute(hgemm<1, 1, 0>, cudaFuncAttributeMaxDynamicSharedMemorySize, SMEM_FF);
    cudaFuncSetAttribute(hgemm<2, 1, 0>, cudaFuncAttributeMaxDynamicSharedMemorySize, SMEM_FF);
    cudaFuncSetAttribute(loop_kernel, cudaFuncAttributeMaxDynamicSharedMemorySize, SMEM_LOOP);

    init_ctrl_kernel<<<1, 256>>>(b_eq, WbProj);
    split_all_kernel<<<(SEG9 + 255) / 256, 256>>>(x, W0, W1, W2, W3, pW0, pW1, pWf, A, WzProj);

    const dim3 tb(256);
    const dim3 gN512(4, 32), gN256(2, 32);

    // feedforward MLP
    hgemm<1, 0, 1><<<gN512, tb, SMEM_FF>>>(sp->xs_h, sp->xs_l, sp->w0h, sp->w0l,
        b0, KPAD0, HID, nullptr, sp->aA_h, sp->aA_l);
    hgemm<1, 0, 1><<<gN512, tb, SMEM_FF>>>(sp->aA_h, sp->aA_l, sp->w1h, sp->w1l,
        b1, HID, HID, nullptr, sp->aB_h, sp->aB_l);
    hgemm<1, 0, 1><<<gN512, tb, SMEM_FF>>>(sp->aB_h, sp->aB_l, sp->w2h, sp->w2l,
        b2, HID, HID, nullptr, sp->aA_h, sp->aA_l);
    hgemm<0, 0, 1><<<gN256, tb, SMEM_FF>>>(sp->aA_h, sp->aA_l, sp->w3h, sp->w3l,
        b3, HID, OUTD, nullptr, sp->z1_h, sp->z1_l);

    // projection net
    hgemm<1, 1, 0><<<gN512, tb, SMEM_FF>>>(sp->z1_h, sp->z1_l, sp->p0h, sp->p0l,
        pb0, OUTD, HID, sp->bufA, nullptr, nullptr);
    ln_split_kernel<<<BSZ, 256>>>(sp->bufA, g0, be0, sp->lA_h, sp->lA_l);
    hgemm<1, 1, 0><<<gN512, tb, SMEM_FF>>>(sp->lA_h, sp->lA_l, sp->p1h, sp->p1l,
        pb1, HID, HID, sp->bufB, nullptr, nullptr);
    ln_split_kernel<<<BSZ, 256>>>(sp->bufB, g1, be1, sp->lB_h, sp->lB_l);
    hgemm<2, 1, 0><<<gN256, tb, SMEM_FF>>>(sp->lB_h, sp->lB_l, sp->pfh, sp->pfl,
        pbf, HID, OUTD, pz, nullptr, nullptr);

    // fused persistent fixed-point loop
    loop_kernel<<<PG, 256, SMEM_LOOP>>>(pz, z_out, b_eq);

    if (out_size > 2 * BSZ * OUTD) write_iter_kernel<<<1, 1>>>(out);
}